// round 5
// baseline (speedup 1.0000x reference)
#include <cuda_runtime.h>

#define N0 16
#define N1 200
#define N2 200
#define NPIX (N1*N2)          // 40000
#define NVOX (N0*NPIX)        // 640000
#define NPHI 190
#define NRAD 223
#define NT 351
#define GR 4                  // gaussian radius
#define NSLOT (NPHI*NRAD)     // 42370
#define NCH 8                 // phi chunks for backprojection
#define CHW 24                // ceil(190/8)

// ---------------- scratch (device globals; no allocation allowed) ----------
__device__ __align__(16) float d_GW[2*GR+1];
__device__ float d_COS[NPHI];
__device__ float d_SIN[NPHI];
__device__ float d_RV[NRAD];
__device__ __align__(16) float d_buf0[NVOX];
__device__ __align__(16) float d_buf1[NVOX];
__device__ __align__(16) float d_st2[2*NVOX];         // paired smoothed img: [(i,j)][{j,j+1}][z]
__device__ __align__(16) float d_zr[NSLOT*N0];        // mult*data/exp, [sidx][z]
__device__ __align__(16) float d_bp[NCH*NVOX];        // backprojection partials

// ---------------- constant tables (match numpy float64 -> float32) ---------
__global__ void k_init()
{
    int t = blockIdx.x * blockDim.x + threadIdx.x;
    if (t == 0) {
        const double sigma = 4.5 / (2.35 * 2.0);
        double g[2*GR+1];
        double sum = 0.0;
        for (int k = 0; k <= 2*GR; k++) {
            double d = (double)(k - GR) / sigma;
            g[k] = exp(-0.5 * d * d);
            sum += g[k];
        }
        for (int k = 0; k <= 2*GR; k++) d_GW[k] = (float)(g[k] / sum);
    }
    const double PI = 3.14159265358979323846;
    for (int i = t; i < NPHI; i += blockDim.x * gridDim.x) {
        float phi = (float)((double)i * (PI / 190.0));   // linspace f64 -> f32
        d_COS[i] = (float)cos((double)phi);
        d_SIN[i] = (float)sin((double)phi);
    }
    for (int i = t; i < NRAD; i += blockDim.x * gridDim.x) {
        d_RV[i] = (float)(-200.0 + (double)i * (400.0 / 222.0));
    }
}

// ---------------- gaussian smoothing (self-adjoint, symmetric padding) -----
__device__ __forceinline__ int refl(int m, int n)
{
    if (m < 0)  m = -1 - m;
    if (m >= n) m = 2*n - 1 - m;
    return m;
}

// smooth along z (axis0). one thread per pixel; all 16 z in registers.
__global__ void k_smooth_z(const float* __restrict__ in, float* __restrict__ out)
{
    int pix = blockIdx.x * blockDim.x + threadIdx.x;
    if (pix >= NPIX) return;
    float v[N0];
    #pragma unroll
    for (int z = 0; z < N0; z++) v[z] = in[z*NPIX + pix];
    #pragma unroll
    for (int z = 0; z < N0; z++) {
        float s = 0.f;
        #pragma unroll
        for (int d = -GR; d <= GR; d++) {
            int m = z + d;
            if (m < 0)  m = -1 - m;
            if (m >= N0) m = 2*N0 - 1 - m;
            s += d_GW[d+GR] * v[m];
        }
        out[z*NPIX + pix] = s;
    }
}

// smooth along i (axis1), layout [z][i][j]
__global__ void k_smooth_i(const float* __restrict__ in, float* __restrict__ out)
{
    int t = blockIdx.x * blockDim.x + threadIdx.x;
    if (t >= NVOX) return;
    int j = t % N2;
    int i = (t / N2) % N1;
    int z = t / NPIX;
    const float* base = in + z*NPIX + j;
    float s = 0.f;
    if (i >= GR && i < N1-GR) {
        #pragma unroll
        for (int d = -GR; d <= GR; d++)
            s += d_GW[d+GR] * base[(i+d) * N2];
    } else {
        #pragma unroll
        for (int d = -GR; d <= GR; d++)
            s += d_GW[d+GR] * base[refl(i+d, N1) * N2];
    }
    out[t] = s;
}

// smooth along j (axis2), layout [z][i][j] -> same layout
__global__ void k_smooth_j(const float* __restrict__ in, float* __restrict__ out)
{
    int t = blockIdx.x * blockDim.x + threadIdx.x;
    if (t >= NVOX) return;
    int j = t % N2;
    int i = (t / N2) % N1;
    int z = t / NPIX;
    const float* base = in + z*NPIX + i*N2;
    float s = 0.f;
    if (j >= GR && j < N2-GR) {
        #pragma unroll
        for (int d = -GR; d <= GR; d++)
            s += d_GW[d+GR] * base[j+d];
    } else {
        #pragma unroll
        for (int d = -GR; d <= GR; d++)
            s += d_GW[d+GR] * base[refl(j+d, N2)];
    }
    out[t] = s;
}

// smooth along j + paired z-transpose via shared memory.
// one block per i row: compute smoothed row into tile[z][j] (coalesced loads),
// then emit out2[((i*N2+j)*2+{0,1})*N0+z] with 16-float contiguous stores.
__global__ void k_smooth_j_t2(const float* __restrict__ in, float* __restrict__ out2)
{
    __shared__ float tile[N0][N2 + 1];   // +1 pad -> conflict-free transposed reads
    int i = blockIdx.x;
    // phase 1: compute (j fastest for coalesced loads)
    for (int t = threadIdx.x; t < N0*N2; t += blockDim.x) {
        int j = t % N2;
        int z = t / N2;
        const float* base = in + z*NPIX + i*N2;
        float s = 0.f;
        if (j >= GR && j < N2-GR) {
            #pragma unroll
            for (int d = -GR; d <= GR; d++)
                s += d_GW[d+GR] * base[j+d];
        } else {
            #pragma unroll
            for (int d = -GR; d <= GR; d++)
                s += d_GW[d+GR] * base[refl(j+d, N2)];
        }
        tile[z][j] = s;
    }
    __syncthreads();
    // phase 2: paired-z writes (z fastest -> contiguous 64B chunks)
    for (int t = threadIdx.x; t < N0*N2; t += blockDim.x) {
        int z = t & (N0-1);
        int j = t >> 4;
        int j1 = min(j + 1, N2 - 1);
        unsigned base = ((unsigned)(i*N2 + j)) << 5;
        out2[base + z]       = tile[z][j];
        out2[base + N0 + z]  = tile[z][j1];
    }
}

// ---------------- forward projection + ratio (fused) ------------------------
// 8 lanes per ray, all at the SAME sample n. The 8 lanes load the 8 float4s of
// one 128B pair-block in a single warp-LDG. Lanes 0-3 accumulate the
// j0-weighted part (z-quads 0-3), lanes 4-7 the j1-weighted part; shfl-reduce
// at the end. Ratio computed in the epilogue.
__global__ void k_project(const float* __restrict__ st2,
                          const float* __restrict__ data,
                          const float* __restrict__ contam,
                          const float* __restrict__ mult,
                          float* __restrict__ zr)
{
    int t = blockIdx.x * blockDim.x + threadIdx.x;
    int lane8 = t & 7;
    int ray   = t >> 3;
    bool live = (ray < NSLOT);
    if (!live) ray = NSLOT - 1;           // clamp: keep all 32 lanes for shfl
    int phi = ray / NRAD;
    int rad = ray - phi * NRAD;
    int zq  = lane8 & 3;
    bool isj1 = lane8 >= 4;

    float c = d_COS[phi], s = d_SIN[phi];
    float r = d_RV[rad];
    float rns = r * (-s);
    float rc  = r * c;

    // ix(n) = A + n*c, iy(n) = B + n*s  (voxel units, n = t sample index)
    float A = 0.5f * (rns + 199.f) - 175.f * c;
    float B = 0.5f * (rc  + 199.f) - 175.f * s;

    const float EPS = 1e-6f;
    float lo = 0.f, hi = 350.f;
    bool empty = false;
    if (fabsf(c) > EPS) {
        float n0 = (0.f   - A) / c;
        float n1 = (199.f - A) / c;
        lo = fmaxf(lo, fminf(n0, n1)); hi = fminf(hi, fmaxf(n0, n1));
    } else if (A < 0.f || A > 199.f) empty = true;
    if (fabsf(s) > EPS) {
        float n0 = (0.f   - B) / s;
        float n1 = (199.f - B) / s;
        lo = fmaxf(lo, fminf(n0, n1)); hi = fminf(hi, fmaxf(n0, n1));
    } else if (B < 0.f || B > 199.f) empty = true;

    float4 acc = make_float4(0.f, 0.f, 0.f, 0.f);
    if (!empty && hi >= lo) {
        int nlo = max(0,    (int)floorf(lo) - 1);
        int nhi = min(NT-1, (int)ceilf (hi) + 1);
        for (int n = nlo; n <= nhi; n++) {
            float tn = -350.f + 2.f * (float)n;
            float ix = (__fmaf_rn(tn, c, rns) + 199.f) * 0.5f;
            float iy = (__fmaf_rn(tn, s, rc ) + 199.f) * 0.5f;
            if (ix < 0.f || ix > 199.f || iy < 0.f || iy > 199.f) continue;
            int i0 = (int)ix;           // floor, ix >= 0
            int j0 = (int)iy;
            float fi = ix - (float)i0;
            float fj = iy - (float)j0;
            float wj = isj1 ? fj : (1.f - fj);
            unsigned base = ((unsigned)(i0*N2 + j0)) << 5;        // floats
            unsigned iofs = (i0 < N1-1) ? (unsigned)(N2*2*N0) : 0u;
            const float4* p0 = (const float4*)(st2 + base) + lane8;
            const float4* p1 = (const float4*)(st2 + base + iofs) + lane8;
            float4 b0 = *p0;
            float4 b1 = *p1;
            float w0 = wj * (1.f - fi);
            float w1 = wj * fi;
            acc.x = __fmaf_rn(w0, b0.x, __fmaf_rn(w1, b1.x, acc.x));
            acc.y = __fmaf_rn(w0, b0.y, __fmaf_rn(w1, b1.y, acc.y));
            acc.z = __fmaf_rn(w0, b0.z, __fmaf_rn(w1, b1.z, acc.z));
            acc.w = __fmaf_rn(w0, b0.w, __fmaf_rn(w1, b1.w, acc.w));
        }
    }

    // combine j0 (lanes 0-3) with j1 (lanes 4-7)
    acc.x += __shfl_down_sync(0xffffffffu, acc.x, 4);
    acc.y += __shfl_down_sync(0xffffffffu, acc.y, 4);
    acc.z += __shfl_down_sync(0xffffffffu, acc.z, 4);
    acc.w += __shfl_down_sync(0xffffffffu, acc.w, 4);

    if (live && !isj1) {
        int sidx = ray;
        float pr[4] = { acc.x*2.f, acc.y*2.f, acc.z*2.f, acc.w*2.f };
        float4 o;
        float* ov = (float*)&o;
        #pragma unroll
        for (int k = 0; k < 4; k++) {
            int gi = (zq*4 + k) * NSLOT + sidx;
            float mm = mult[gi];
            float e  = __fmaf_rn(mm, pr[k], contam[gi]);   // exp = mult*fwd + contam
            ov[k] = mm * data[gi] / e;                     // mult * (data/exp)
        }
        ((float4*)zr)[sidx*4 + zq] = o;
    }
}

// ---------------- backprojection (exact adjoint, gather form) ---------------
// one thread = (pixel, phi-chunk). All 16 z accumulated; W computed once.
// Interior pixels use the rotated incremental form:
//   ix - i = ((t - t0) c - (r - r0) s)/2 = a   (a += c per n-step)
//   iy - j = ((t - t0) s + (r - r0) c)/2 = b   (b += s per n-step)
// Tent support |a|<1,|b|<1 guarantees validity for i,j in [1,198].
__global__ void k_backproject(const float* __restrict__ zr, float* __restrict__ bp)
{
    int tid = blockIdx.x * blockDim.x + threadIdx.x;
    if (tid >= NCH * NPIX) return;
    int pix = tid % NPIX;
    int ch  = tid / NPIX;
    int i = pix / N2, j = pix % N2;
    float X = -199.f + 2.f * (float)i;
    float Y = -199.f + 2.f * (float)j;

    float acc[N0];
    #pragma unroll
    for (int k = 0; k < N0; k++) acc[k] = 0.f;

    const float inv_dr = (float)(222.0 / 400.0);
    float fi_f = (float)i, fj_f = (float)j;
    bool interior = (i >= 1 && i <= N1-2 && j >= 1 && j <= N2-2);

    int plo = ch * CHW;
    int phi_end = min(NPHI, plo + CHW);

    for (int phi = plo; phi < phi_end; phi++) {
        float c = d_COS[phi], s = d_SIN[phi];
        float lim = 2.f * (fabsf(c) + fabsf(s)) + 1e-2f;   // tight tent support
        float r0 = -X*s + Y*c;   // projection of voxel onto perp(phi)
        float t0 =  X*c + Y*s;   // projection onto dir(phi)
        int mlo = max(0,      (int)ceilf ((r0 + 200.f - lim) * inv_dr));
        int mhi = min(NRAD-1, (int)floorf((r0 + 200.f + lim) * inv_dr));
        int nlo = max(0,      (int)ceilf ((t0 + 350.f - lim) * 0.5f));
        int nhi = min(NT-1,   (int)floorf((t0 + 350.f + lim) * 0.5f));
        int ncnt = nhi - nlo;
        if (ncnt < 0 || mhi < mlo) continue;

        if (interior) {
            float hc = 0.5f * c, hs = 0.5f * s;
            float dt0 = (-350.f + 2.f * (float)nlo) - t0;
            float a00 = dt0 * hc;
            float b00 = dt0 * hs;
            for (int m = mlo; m <= mhi; m++) {
                float dr = d_RV[m] - r0;
                float a = __fmaf_rn(-dr, hs, a00);
                float b = __fmaf_rn( dr, hc, b00);
                float W = 0.f;
                for (int n = 0; n <= ncnt; n++) {
                    float wx = 1.f - fabsf(a);
                    float wy = 1.f - fabsf(b);
                    if (wx > 0.f && wy > 0.f) W = __fmaf_rn(wx, wy, W);
                    a += c; b += s;
                }
                if (W != 0.f) {
                    const float4* zp = (const float4*)(zr + (phi*NRAD + m)*N0);
                    float4 va = zp[0], vb = zp[1], vc = zp[2], vd = zp[3];
                    acc[0]  += W*va.x; acc[1]  += W*va.y; acc[2]  += W*va.z; acc[3]  += W*va.w;
                    acc[4]  += W*vb.x; acc[5]  += W*vb.y; acc[6]  += W*vb.z; acc[7]  += W*vb.w;
                    acc[8]  += W*vc.x; acc[9]  += W*vc.y; acc[10] += W*vc.z; acc[11] += W*vc.w;
                    acc[12] += W*vd.x; acc[13] += W*vd.y; acc[14] += W*vd.z; acc[15] += W*vd.w;
                }
            }
        } else {
            for (int m = mlo; m <= mhi; m++) {
                float rm  = d_RV[m];
                float rns = rm * (-s);
                float rc  = rm * c;
                float W = 0.f;
                for (int n = nlo; n <= nhi; n++) {
                    float tn = -350.f + 2.f * (float)n;
                    float ix = (__fmaf_rn(tn, c, rns) + 199.f) * 0.5f;
                    float iy = (__fmaf_rn(tn, s, rc ) + 199.f) * 0.5f;
                    if (ix < 0.f || ix > 199.f || iy < 0.f || iy > 199.f) continue;
                    float wx = 1.f - fabsf(ix - fi_f);
                    float wy = 1.f - fabsf(iy - fj_f);
                    if (wx > 0.f && wy > 0.f) W = __fmaf_rn(wx, wy, W);
                }
                if (W != 0.f) {
                    const float4* zp = (const float4*)(zr + (phi*NRAD + m)*N0);
                    float4 va = zp[0], vb = zp[1], vc = zp[2], vd = zp[3];
                    acc[0]  += W*va.x; acc[1]  += W*va.y; acc[2]  += W*va.z; acc[3]  += W*va.w;
                    acc[4]  += W*vb.x; acc[5]  += W*vb.y; acc[6]  += W*vb.z; acc[7]  += W*vb.w;
                    acc[8]  += W*vc.x; acc[9]  += W*vc.y; acc[10] += W*vc.z; acc[11] += W*vc.w;
                    acc[12] += W*vd.x; acc[13] += W*vd.y; acc[14] += W*vd.z; acc[15] += W*vd.w;
                }
            }
        }
    }
    float* dst = bp + ch * NVOX;
    #pragma unroll
    for (int k = 0; k < N0; k++)
        dst[k*NPIX + pix] = acc[k] * 2.f;   // * STEP
}

// ---------------- combine partial backprojections (float4) ------------------
__global__ void k_combine(const float* __restrict__ bp, float* __restrict__ g)
{
    int t = blockIdx.x * blockDim.x + threadIdx.x;
    if (t >= NVOX/4) return;
    float4 s = make_float4(0.f, 0.f, 0.f, 0.f);
    #pragma unroll
    for (int c = 0; c < NCH; c++) {
        float4 v = ((const float4*)bp)[c*(NVOX/4) + t];
        s.x += v.x; s.y += v.y; s.z += v.z; s.w += v.w;
    }
    ((float4*)g)[t] = s;
}

// ---------------- final z-smoothing + MLEM update ---------------------------
__global__ void k_smooth_z_final(const float* __restrict__ gin,
                                 const float* __restrict__ x,
                                 const float* __restrict__ sens,
                                 float* __restrict__ out)
{
    int pix = blockIdx.x * blockDim.x + threadIdx.x;
    if (pix >= NPIX) return;
    float v[N0];
    #pragma unroll
    for (int z = 0; z < N0; z++) v[z] = gin[z*NPIX + pix];
    #pragma unroll
    for (int z = 0; z < N0; z++) {
        float s = 0.f;
        #pragma unroll
        for (int d = -GR; d <= GR; d++) {
            int m = z + d;
            if (m < 0)  m = -1 - m;
            if (m >= N0) m = 2*N0 - 1 - m;
            s += d_GW[d+GR] * v[m];
        }
        int gi = z*NPIX + pix;
        out[gi] = x[gi] * s / sens[gi];
    }
}

// ---------------- launch ----------------------------------------------------
extern "C" void kernel_launch(void* const* d_in, const int* in_sizes, int n_in,
                              void* d_out, int out_size)
{
    const float* x      = (const float*)d_in[0];
    const float* data   = (const float*)d_in[1];
    const float* contam = (const float*)d_in[2];
    const float* mult   = (const float*)d_in[3];
    const float* sens   = (const float*)d_in[4];
    float* out = (float*)d_out;

    float *buf0, *buf1, *st2, *zr, *bp;
    cudaGetSymbolAddress((void**)&buf0, d_buf0);
    cudaGetSymbolAddress((void**)&buf1, d_buf1);
    cudaGetSymbolAddress((void**)&st2,  d_st2);
    cudaGetSymbolAddress((void**)&zr,   d_zr);
    cudaGetSymbolAddress((void**)&bp,   d_bp);

    k_init<<<1, 256>>>();

    // forward: gauss3(x) -> paired transposed smoothed image
    k_smooth_z   <<<(NPIX + 255)/256, 256>>>(x, buf0);
    k_smooth_i   <<<(NVOX + 255)/256, 256>>>(buf0, buf1);
    k_smooth_j_t2<<<N1, 256>>>(buf1, st2);

    // project + exp + ratio (fused, 8 lanes/ray)
    k_project<<<(NSLOT*8 + 255)/256, 256>>>(st2, data, contam, mult, zr);

    // adjoint: backproject (phi-chunked), combine, then gauss3 reversed
    k_backproject<<<(NCH*NPIX + 255)/256, 256>>>(zr, bp);
    k_combine<<<(NVOX/4 + 255)/256, 256>>>(bp, buf0);
    k_smooth_j<<<(NVOX + 255)/256, 256>>>(buf0, buf1);
    k_smooth_i<<<(NVOX + 255)/256, 256>>>(buf1, buf0);
    k_smooth_z_final<<<(NPIX + 255)/256, 256>>>(buf0, x, sens, out);
}

// round 6
// speedup vs baseline: 1.1035x; 1.1035x over previous
#include <cuda_runtime.h>

#define N0 16
#define N1 200
#define N2 200
#define NPIX (N1*N2)          // 40000
#define NVOX (N0*NPIX)        // 640000
#define NPHI 190
#define NRAD 223
#define NT 351
#define GR 4                  // gaussian radius
#define NSLOT (NPHI*NRAD)     // 42370
#define NCH 8                 // phi chunks for backprojection
#define CHW 24                // ceil(190/8)

// ---------------- scratch (device globals; no allocation allowed) ----------
__device__ __align__(16) float d_GW[2*GR+1];
__device__ float d_COS[NPHI];
__device__ float d_SIN[NPHI];
__device__ float d_RV[NRAD];
__device__ __align__(16) float d_buf0[NVOX];
__device__ __align__(16) float d_buf1[NVOX];
__device__ __align__(16) float d_st2[2*NVOX];         // paired smoothed img: [(i,j)][{j,j+1}][z]
__device__ __align__(16) float d_zr[NSLOT*N0];        // mult*data/exp, [sidx][z]
__device__ __align__(16) float d_bp[NCH*NVOX];        // backprojection partials

// ---------------- constant tables (match numpy float64 -> float32) ---------
__global__ void k_init()
{
    int t = blockIdx.x * blockDim.x + threadIdx.x;
    if (t == 0) {
        const double sigma = 4.5 / (2.35 * 2.0);
        double g[2*GR+1];
        double sum = 0.0;
        for (int k = 0; k <= 2*GR; k++) {
            double d = (double)(k - GR) / sigma;
            g[k] = exp(-0.5 * d * d);
            sum += g[k];
        }
        for (int k = 0; k <= 2*GR; k++) d_GW[k] = (float)(g[k] / sum);
    }
    const double PI = 3.14159265358979323846;
    for (int i = t; i < NPHI; i += blockDim.x * gridDim.x) {
        float phi = (float)((double)i * (PI / 190.0));   // linspace f64 -> f32
        d_COS[i] = (float)cos((double)phi);
        d_SIN[i] = (float)sin((double)phi);
    }
    for (int i = t; i < NRAD; i += blockDim.x * gridDim.x) {
        d_RV[i] = (float)(-200.0 + (double)i * (400.0 / 222.0));
    }
}

// ---------------- gaussian smoothing (self-adjoint, symmetric padding) -----
__device__ __forceinline__ int refl(int m, int n)
{
    if (m < 0)  m = -1 - m;
    if (m >= n) m = 2*n - 1 - m;
    return m;
}

// smooth along i (axis1), layout [z][i][j]
__global__ void k_smooth_i(const float* __restrict__ in, float* __restrict__ out)
{
    int t = blockIdx.x * blockDim.x + threadIdx.x;
    if (t >= NVOX) return;
    int j = t % N2;
    int i = (t / N2) % N1;
    int z = t / NPIX;
    const float* base = in + z*NPIX + j;
    float s = 0.f;
    if (i >= GR && i < N1-GR) {
        #pragma unroll
        for (int d = -GR; d <= GR; d++)
            s += d_GW[d+GR] * base[(i+d) * N2];
    } else {
        #pragma unroll
        for (int d = -GR; d <= GR; d++)
            s += d_GW[d+GR] * base[refl(i+d, N1) * N2];
    }
    out[t] = s;
}

// smooth along j (axis2), layout [z][i][j] -> same layout
__global__ void k_smooth_j(const float* __restrict__ in, float* __restrict__ out)
{
    int t = blockIdx.x * blockDim.x + threadIdx.x;
    if (t >= NVOX) return;
    int j = t % N2;
    int i = (t / N2) % N1;
    int z = t / NPIX;
    const float* base = in + z*NPIX + i*N2;
    float s = 0.f;
    if (j >= GR && j < N2-GR) {
        #pragma unroll
        for (int d = -GR; d <= GR; d++)
            s += d_GW[d+GR] * base[j+d];
    } else {
        #pragma unroll
        for (int d = -GR; d <= GR; d++)
            s += d_GW[d+GR] * base[refl(j+d, N2)];
    }
    out[t] = s;
}

// fused: smooth along j, then along z, then write paired z-transposed layout:
// out2[((i*N2+j)*2 + 0)*N0 + z] = v(i, j,   z)
// out2[((i*N2+j)*2 + 1)*N0 + z] = v(i, j+1, z)   (j+1 clamped at N2-1)
// one block per i row.
__global__ void k_smooth_jz_t2(const float* __restrict__ in, float* __restrict__ out2)
{
    __shared__ float tj[N0][N2 + 1];     // j-smoothed
    __shared__ float tz[N0][N2 + 1];     // j+z smoothed
    int i = blockIdx.x;
    // phase 1: j-smooth (j fastest for coalesced loads)
    for (int t = threadIdx.x; t < N0*N2; t += blockDim.x) {
        int j = t % N2;
        int z = t / N2;
        const float* base = in + z*NPIX + i*N2;
        float s = 0.f;
        if (j >= GR && j < N2-GR) {
            #pragma unroll
            for (int d = -GR; d <= GR; d++)
                s += d_GW[d+GR] * base[j+d];
        } else {
            #pragma unroll
            for (int d = -GR; d <= GR; d++)
                s += d_GW[d+GR] * base[refl(j+d, N2)];
        }
        tj[z][j] = s;
    }
    __syncthreads();
    // phase 2: z-smooth (symmetric reflection on 16-deep axis)
    for (int t = threadIdx.x; t < N0*N2; t += blockDim.x) {
        int j = t % N2;
        int z = t / N2;
        float s = 0.f;
        #pragma unroll
        for (int d = -GR; d <= GR; d++) {
            int m = z + d;
            if (m < 0)   m = -1 - m;
            if (m >= N0) m = 2*N0 - 1 - m;
            s += d_GW[d+GR] * tj[m][j];
        }
        tz[z][j] = s;
    }
    __syncthreads();
    // phase 3: paired-z writes (z fastest -> contiguous 64B chunks)
    for (int t = threadIdx.x; t < N0*N2; t += blockDim.x) {
        int z = t & (N0-1);
        int j = t >> 4;
        int j1 = min(j + 1, N2 - 1);
        unsigned base = ((unsigned)(i*N2 + j)) << 5;
        out2[base + z]      = tz[z][j];
        out2[base + N0 + z] = tz[z][j1];
    }
}

// ---------------- forward projection + ratio (fused) ------------------------
// 8 lanes per ray, all at the SAME sample n. The 8 lanes load the 8 float4s of
// one 128B pair-block in a single warp-LDG. Lanes 0-3 accumulate the
// j0-weighted part (z-quads 0-3), lanes 4-7 the j1-weighted part; shfl-reduce
// at the end. Ratio computed in the epilogue.
__global__ void k_project(const float* __restrict__ st2,
                          const float* __restrict__ data,
                          const float* __restrict__ contam,
                          const float* __restrict__ mult,
                          float* __restrict__ zr)
{
    int t = blockIdx.x * blockDim.x + threadIdx.x;
    int lane8 = t & 7;
    int ray   = t >> 3;
    bool live = (ray < NSLOT);
    if (!live) ray = NSLOT - 1;           // clamp: keep all 32 lanes for shfl
    int phi = ray / NRAD;
    int rad = ray - phi * NRAD;
    int zq  = lane8 & 3;
    bool isj1 = lane8 >= 4;

    float c = d_COS[phi], s = d_SIN[phi];
    float r = d_RV[rad];
    float rns = r * (-s);
    float rc  = r * c;

    // ix(n) = A + n*c, iy(n) = B + n*s  (voxel units, n = t sample index)
    float A = 0.5f * (rns + 199.f) - 175.f * c;
    float B = 0.5f * (rc  + 199.f) - 175.f * s;

    const float EPS = 1e-6f;
    float lo = 0.f, hi = 350.f;
    bool empty = false;
    if (fabsf(c) > EPS) {
        float n0 = (0.f   - A) / c;
        float n1 = (199.f - A) / c;
        lo = fmaxf(lo, fminf(n0, n1)); hi = fminf(hi, fmaxf(n0, n1));
    } else if (A < 0.f || A > 199.f) empty = true;
    if (fabsf(s) > EPS) {
        float n0 = (0.f   - B) / s;
        float n1 = (199.f - B) / s;
        lo = fmaxf(lo, fminf(n0, n1)); hi = fminf(hi, fmaxf(n0, n1));
    } else if (B < 0.f || B > 199.f) empty = true;

    float4 acc = make_float4(0.f, 0.f, 0.f, 0.f);
    if (!empty && hi >= lo) {
        int nlo = max(0,    (int)floorf(lo) - 1);
        int nhi = min(NT-1, (int)ceilf (hi) + 1);
        for (int n = nlo; n <= nhi; n++) {
            float tn = -350.f + 2.f * (float)n;
            float ix = (__fmaf_rn(tn, c, rns) + 199.f) * 0.5f;
            float iy = (__fmaf_rn(tn, s, rc ) + 199.f) * 0.5f;
            if (ix < 0.f || ix > 199.f || iy < 0.f || iy > 199.f) continue;
            int i0 = (int)ix;           // floor, ix >= 0
            int j0 = (int)iy;
            float fi = ix - (float)i0;
            float fj = iy - (float)j0;
            float wj = isj1 ? fj : (1.f - fj);
            unsigned base = ((unsigned)(i0*N2 + j0)) << 5;        // floats
            unsigned iofs = (i0 < N1-1) ? (unsigned)(N2*2*N0) : 0u;
            const float4* p0 = (const float4*)(st2 + base) + lane8;
            const float4* p1 = (const float4*)(st2 + base + iofs) + lane8;
            float4 b0 = *p0;
            float4 b1 = *p1;
            float w0 = wj * (1.f - fi);
            float w1 = wj * fi;
            acc.x = __fmaf_rn(w0, b0.x, __fmaf_rn(w1, b1.x, acc.x));
            acc.y = __fmaf_rn(w0, b0.y, __fmaf_rn(w1, b1.y, acc.y));
            acc.z = __fmaf_rn(w0, b0.z, __fmaf_rn(w1, b1.z, acc.z));
            acc.w = __fmaf_rn(w0, b0.w, __fmaf_rn(w1, b1.w, acc.w));
        }
    }

    // combine j0 (lanes 0-3) with j1 (lanes 4-7)
    acc.x += __shfl_down_sync(0xffffffffu, acc.x, 4);
    acc.y += __shfl_down_sync(0xffffffffu, acc.y, 4);
    acc.z += __shfl_down_sync(0xffffffffu, acc.z, 4);
    acc.w += __shfl_down_sync(0xffffffffu, acc.w, 4);

    if (live && !isj1) {
        int sidx = ray;
        float pr[4] = { acc.x*2.f, acc.y*2.f, acc.z*2.f, acc.w*2.f };
        float4 o;
        float* ov = (float*)&o;
        #pragma unroll
        for (int k = 0; k < 4; k++) {
            int gi = (zq*4 + k) * NSLOT + sidx;
            float mm = mult[gi];
            float e  = __fmaf_rn(mm, pr[k], contam[gi]);   // exp = mult*fwd + contam
            ov[k] = mm * data[gi] / e;                     // mult * (data/exp)
        }
        ((float4*)zr)[sidx*4 + zq] = o;
    }
}

// ---------------- backprojection (exact adjoint, gather form) ---------------
// one thread = (pixel, phi-chunk). All 16 z accumulated; W computed once.
// Interior pixels skip the ix/iy bounds test (tent support implies validity);
// same loop body both paths (round-4 version; round-5 incremental form regressed).
__global__ void k_backproject(const float* __restrict__ zr, float* __restrict__ bp)
{
    int tid = blockIdx.x * blockDim.x + threadIdx.x;
    if (tid >= NCH * NPIX) return;
    int pix = tid % NPIX;
    int ch  = tid / NPIX;
    int i = pix / N2, j = pix % N2;
    float X = -199.f + 2.f * (float)i;
    float Y = -199.f + 2.f * (float)j;

    float acc[N0];
    #pragma unroll
    for (int k = 0; k < N0; k++) acc[k] = 0.f;

    const float inv_dr = (float)(222.0 / 400.0);
    float fi_f = (float)i, fj_f = (float)j;
    bool interior = (i >= 1 && i <= N1-2 && j >= 1 && j <= N2-2);

    int plo = ch * CHW;
    int phi_end = min(NPHI, plo + CHW);

    for (int phi = plo; phi < phi_end; phi++) {
        float c = d_COS[phi], s = d_SIN[phi];
        float lim = 2.f * (fabsf(c) + fabsf(s)) + 1e-2f;   // tight tent support
        float r0 = -X*s + Y*c;   // projection of voxel onto perp(phi)
        float t0 =  X*c + Y*s;   // projection onto dir(phi)
        int mlo = max(0,      (int)ceilf ((r0 + 200.f - lim) * inv_dr));
        int mhi = min(NRAD-1, (int)floorf((r0 + 200.f + lim) * inv_dr));
        int nlo = max(0,      (int)ceilf ((t0 + 350.f - lim) * 0.5f));
        int nhi = min(NT-1,   (int)floorf((t0 + 350.f + lim) * 0.5f));
        for (int m = mlo; m <= mhi; m++) {
            float rm  = d_RV[m];
            float rns = rm * (-s);
            float rc  = rm * c;
            float W = 0.f;
            if (interior) {
                for (int n = nlo; n <= nhi; n++) {
                    float tn = -350.f + 2.f * (float)n;
                    float ix = (__fmaf_rn(tn, c, rns) + 199.f) * 0.5f;
                    float iy = (__fmaf_rn(tn, s, rc ) + 199.f) * 0.5f;
                    float wx = 1.f - fabsf(ix - fi_f);
                    float wy = 1.f - fabsf(iy - fj_f);
                    if (wx > 0.f && wy > 0.f) W = __fmaf_rn(wx, wy, W);
                }
            } else {
                for (int n = nlo; n <= nhi; n++) {
                    float tn = -350.f + 2.f * (float)n;
                    float ix = (__fmaf_rn(tn, c, rns) + 199.f) * 0.5f;
                    float iy = (__fmaf_rn(tn, s, rc ) + 199.f) * 0.5f;
                    if (ix < 0.f || ix > 199.f || iy < 0.f || iy > 199.f) continue;
                    float wx = 1.f - fabsf(ix - fi_f);
                    float wy = 1.f - fabsf(iy - fj_f);
                    if (wx > 0.f && wy > 0.f) W = __fmaf_rn(wx, wy, W);
                }
            }
            if (W != 0.f) {
                const float4* zp = (const float4*)(zr + (phi*NRAD + m)*N0);
                float4 a = zp[0], b = zp[1], cc = zp[2], dd = zp[3];
                acc[0]  += W*a.x;  acc[1]  += W*a.y;  acc[2]  += W*a.z;  acc[3]  += W*a.w;
                acc[4]  += W*b.x;  acc[5]  += W*b.y;  acc[6]  += W*b.z;  acc[7]  += W*b.w;
                acc[8]  += W*cc.x; acc[9]  += W*cc.y; acc[10] += W*cc.z; acc[11] += W*cc.w;
                acc[12] += W*dd.x; acc[13] += W*dd.y; acc[14] += W*dd.z; acc[15] += W*dd.w;
            }
        }
    }
    float* dst = bp + ch * NVOX;
    #pragma unroll
    for (int k = 0; k < N0; k++)
        dst[k*NPIX + pix] = acc[k] * 2.f;   // * STEP
}

// ---------------- combine partial backprojections (float4) ------------------
__global__ void k_combine(const float* __restrict__ bp, float* __restrict__ g)
{
    int t = blockIdx.x * blockDim.x + threadIdx.x;
    if (t >= NVOX/4) return;
    float4 s = make_float4(0.f, 0.f, 0.f, 0.f);
    #pragma unroll
    for (int c = 0; c < NCH; c++) {
        float4 v = ((const float4*)bp)[c*(NVOX/4) + t];
        s.x += v.x; s.y += v.y; s.z += v.z; s.w += v.w;
    }
    ((float4*)g)[t] = s;
}

// ---------------- final z-smoothing + MLEM update ---------------------------
__global__ void k_smooth_z_final(const float* __restrict__ gin,
                                 const float* __restrict__ x,
                                 const float* __restrict__ sens,
                                 float* __restrict__ out)
{
    int pix = blockIdx.x * blockDim.x + threadIdx.x;
    if (pix >= NPIX) return;
    float v[N0];
    #pragma unroll
    for (int z = 0; z < N0; z++) v[z] = gin[z*NPIX + pix];
    #pragma unroll
    for (int z = 0; z < N0; z++) {
        float s = 0.f;
        #pragma unroll
        for (int d = -GR; d <= GR; d++) {
            int m = z + d;
            if (m < 0)  m = -1 - m;
            if (m >= N0) m = 2*N0 - 1 - m;
            s += d_GW[d+GR] * v[m];
        }
        int gi = z*NPIX + pix;
        out[gi] = x[gi] * s / sens[gi];
    }
}

// ---------------- launch ----------------------------------------------------
extern "C" void kernel_launch(void* const* d_in, const int* in_sizes, int n_in,
                              void* d_out, int out_size)
{
    const float* x      = (const float*)d_in[0];
    const float* data   = (const float*)d_in[1];
    const float* contam = (const float*)d_in[2];
    const float* mult   = (const float*)d_in[3];
    const float* sens   = (const float*)d_in[4];
    float* out = (float*)d_out;

    float *buf0, *buf1, *st2, *zr, *bp;
    cudaGetSymbolAddress((void**)&buf0, d_buf0);
    cudaGetSymbolAddress((void**)&buf1, d_buf1);
    cudaGetSymbolAddress((void**)&st2,  d_st2);
    cudaGetSymbolAddress((void**)&zr,   d_zr);
    cudaGetSymbolAddress((void**)&bp,   d_bp);

    k_init<<<1, 256>>>();

    // forward: gauss3(x) (axes commute: i, then fused j+z) -> paired transposed image
    k_smooth_i    <<<(NVOX + 255)/256, 256>>>(x, buf0);
    k_smooth_jz_t2<<<N1, 512>>>(buf0, st2);

    // project + exp + ratio (fused, 8 lanes/ray)  [launch #4 -> ncu capture]
    k_project<<<(NSLOT*8 + 255)/256, 256>>>(st2, data, contam, mult, zr);

    // adjoint: backproject (phi-chunked), combine, then gauss3 reversed
    k_backproject<<<(NCH*NPIX + 255)/256, 256>>>(zr, bp);
    k_combine<<<(NVOX/4 + 255)/256, 256>>>(bp, buf0);
    k_smooth_j<<<(NVOX + 255)/256, 256>>>(buf0, buf1);
    k_smooth_i<<<(NVOX + 255)/256, 256>>>(buf1, buf0);
    k_smooth_z_final<<<(NPIX + 255)/256, 256>>>(buf0, x, sens, out);
}

// round 7
// speedup vs baseline: 1.1476x; 1.0400x over previous
#include <cuda_runtime.h>

#define N0 16
#define N1 200
#define N2 200
#define NPIX (N1*N2)          // 40000
#define NVOX (N0*NPIX)        // 640000
#define NPHI 190
#define NRAD 223
#define NT 351
#define GR 4                  // gaussian radius
#define NSLOT (NPHI*NRAD)     // 42370
#define NCH 8                 // phi chunks for backprojection
#define CHW 24                // ceil(190/8)

// ---------------- scratch (device globals; no allocation allowed) ----------
__device__ __align__(16) float d_GW[2*GR+1];
__device__ float d_COS[NPHI];
__device__ float d_SIN[NPHI];
__device__ float d_RV[NRAD];
__device__ __align__(16) float d_buf0[NVOX];
__device__ __align__(16) float d_buf1[NVOX];
__device__ __align__(16) float d_st2[2*NVOX + 2*N0*N2];  // paired img + pad i-row
__device__ __align__(16) float d_zr[NSLOT*N0];           // mult*data/exp, [sidx][z]
__device__ __align__(16) float d_bp[NCH*NVOX];           // backprojection partials

// ---------------- packed f32x2 helpers (Blackwell) --------------------------
__device__ __forceinline__ unsigned long long f2_pack(float a, float b)
{
    unsigned long long r;
    asm("mov.b64 %0, {%1,%2};" : "=l"(r) : "f"(a), "f"(b));
    return r;
}
__device__ __forceinline__ unsigned long long f2_packu(unsigned a, unsigned b)
{
    unsigned long long r;
    asm("mov.b64 %0, {%1,%2};" : "=l"(r) : "r"(a), "r"(b));
    return r;
}
__device__ __forceinline__ void f2_fma(unsigned long long& d,
                                       unsigned long long a, unsigned long long b)
{
    asm("fma.rn.f32x2 %0, %1, %2, %0;" : "+l"(d) : "l"(a), "l"(b));
}
__device__ __forceinline__ unsigned long long f2_add(unsigned long long a,
                                                     unsigned long long b)
{
    unsigned long long r;
    asm("add.rn.f32x2 %0, %1, %2;" : "=l"(r) : "l"(a), "l"(b));
    return r;
}
__device__ __forceinline__ float2 f2_unpack(unsigned long long v)
{
    float2 r;
    asm("mov.b64 {%0,%1}, %2;" : "=f"(r.x), "=f"(r.y) : "l"(v));
    return r;
}

// ---------------- constant tables (match numpy float64 -> float32) ---------
__global__ void k_init()
{
    int t = blockIdx.x * blockDim.x + threadIdx.x;
    if (t == 0) {
        const double sigma = 4.5 / (2.35 * 2.0);
        double g[2*GR+1];
        double sum = 0.0;
        for (int k = 0; k <= 2*GR; k++) {
            double d = (double)(k - GR) / sigma;
            g[k] = exp(-0.5 * d * d);
            sum += g[k];
        }
        for (int k = 0; k <= 2*GR; k++) d_GW[k] = (float)(g[k] / sum);
    }
    const double PI = 3.14159265358979323846;
    for (int i = t; i < NPHI; i += blockDim.x * gridDim.x) {
        float phi = (float)((double)i * (PI / 190.0));   // linspace f64 -> f32
        d_COS[i] = (float)cos((double)phi);
        d_SIN[i] = (float)sin((double)phi);
    }
    for (int i = t; i < NRAD; i += blockDim.x * gridDim.x) {
        d_RV[i] = (float)(-200.0 + (double)i * (400.0 / 222.0));
    }
}

__device__ __forceinline__ int refl(int m, int n)
{
    if (m < 0)  m = -1 - m;
    if (m >= n) m = 2*n - 1 - m;
    return m;
}

// ---------------- fused forward gauss3 + paired z-transpose -----------------
// one block per i row: i-smooth (global reads), j-smooth, z-smooth in smem,
// then write paired z-innermost layout:
//   out2[((i*N2+j)*2 + 0)*N0 + z] = v(i, j,   z)
//   out2[((i*N2+j)*2 + 1)*N0 + z] = v(i, j+1, z)  (j+1 clamped)
// plus a duplicate pad row at i = N1 (copy of i = N1-1).
__global__ void k_gauss3t2(const float* __restrict__ in, float* __restrict__ out2)
{
    __shared__ float ta[N0][N2 + 1];
    __shared__ float tb[N0][N2 + 1];
    int i = blockIdx.x;
    int ridx[2*GR+1];
    #pragma unroll
    for (int d = -GR; d <= GR; d++) ridx[d+GR] = refl(i + d, N1);
    // phase 1: i-smooth
    for (int t = threadIdx.x; t < N0*N2; t += blockDim.x) {
        int j = t % N2;
        int z = t / N2;
        const float* base = in + z*NPIX + j;
        float s = 0.f;
        #pragma unroll
        for (int d = 0; d < 2*GR+1; d++)
            s += d_GW[d] * base[ridx[d]*N2];
        ta[z][j] = s;
    }
    __syncthreads();
    // phase 2: j-smooth (ta -> tb)
    for (int t = threadIdx.x; t < N0*N2; t += blockDim.x) {
        int j = t % N2;
        int z = t / N2;
        float s = 0.f;
        if (j >= GR && j < N2-GR) {
            #pragma unroll
            for (int d = -GR; d <= GR; d++)
                s += d_GW[d+GR] * ta[z][j+d];
        } else {
            #pragma unroll
            for (int d = -GR; d <= GR; d++)
                s += d_GW[d+GR] * ta[z][refl(j+d, N2)];
        }
        tb[z][j] = s;
    }
    __syncthreads();
    // phase 3: z-smooth (tb -> ta)
    for (int t = threadIdx.x; t < N0*N2; t += blockDim.x) {
        int j = t % N2;
        int z = t / N2;
        float s = 0.f;
        #pragma unroll
        for (int d = -GR; d <= GR; d++) {
            int m = z + d;
            if (m < 0)   m = -1 - m;
            if (m >= N0) m = 2*N0 - 1 - m;
            s += d_GW[d+GR] * tb[m][j];
        }
        ta[z][j] = s;
    }
    __syncthreads();
    // phase 4: paired-z writes (z fastest -> contiguous chunks)
    for (int t = threadIdx.x; t < N0*N2; t += blockDim.x) {
        int z = t & (N0-1);
        int j = t >> 4;
        int j1 = min(j + 1, N2 - 1);
        float v0 = ta[z][j];
        float v1 = ta[z][j1];
        unsigned base = ((unsigned)(i*N2 + j)) << 5;
        out2[base + z]      = v0;
        out2[base + N0 + z] = v1;
        if (i == N1-1) {   // pad row i = N1 duplicates i = N1-1
            unsigned pbase = ((unsigned)(N1*N2 + j)) << 5;
            out2[pbase + z]      = v0;
            out2[pbase + N0 + z] = v1;
        }
    }
}

// ---------------- forward projection + ratio (fused) ------------------------
// 8 lanes per ray, all at the SAME sample n; lanes load the 8 float4s of one
// 128B pair-block in a single warp-LDG. Lanes 0-3: j0-weighted part, 4-7: j1.
// Incremental tn, folded half-scaling, packed f32x2 accumulate.
__global__ void k_project(const float* __restrict__ st2,
                          const float* __restrict__ data,
                          const float* __restrict__ contam,
                          const float* __restrict__ mult,
                          float* __restrict__ zr)
{
    int t = blockIdx.x * blockDim.x + threadIdx.x;
    int lane8 = t & 7;
    int ray   = t >> 3;
    bool live = (ray < NSLOT);
    if (!live) ray = NSLOT - 1;           // clamp: keep all 32 lanes for shfl
    int phi = ray / NRAD;
    int rad = ray - phi * NRAD;
    int zq  = lane8 & 3;
    bool isj1 = lane8 >= 4;

    float c = d_COS[phi], s = d_SIN[phi];
    float r = d_RV[rad];
    float rns = r * (-s);
    float rc  = r * c;

    // ix(n) = A + n*c, iy(n) = B + n*s  (voxel units, n = t sample index)
    float A = 0.5f * (rns + 199.f) - 175.f * c;
    float B = 0.5f * (rc  + 199.f) - 175.f * s;

    const float EPS = 1e-6f;
    float lo = 0.f, hi = 350.f;
    bool empty = false;
    if (fabsf(c) > EPS) {
        float n0 = (0.f   - A) / c;
        float n1 = (199.f - A) / c;
        lo = fmaxf(lo, fminf(n0, n1)); hi = fminf(hi, fmaxf(n0, n1));
    } else if (A < 0.f || A > 199.f) empty = true;
    if (fabsf(s) > EPS) {
        float n0 = (0.f   - B) / s;
        float n1 = (199.f - B) / s;
        lo = fmaxf(lo, fminf(n0, n1)); hi = fminf(hi, fmaxf(n0, n1));
    } else if (B < 0.f || B > 199.f) empty = true;

    unsigned long long acc01 = 0ull, acc23 = 0ull;
    if (!empty && hi >= lo) {
        int nlo = max(0,    (int)floorf(lo) - 1);
        int nhi = min(NT-1, (int)ceilf (hi) + 1);
        float hc = 0.5f * c, hs = 0.5f * s;
        float Kx = 0.5f * (rns + 199.f);
        float Ky = 0.5f * (rc  + 199.f);
        float tn = -350.f + 2.f * (float)nlo;
        for (int n = nlo; n <= nhi; n++, tn += 2.f) {
            float ix = __fmaf_rn(tn, hc, Kx);
            float iy = __fmaf_rn(tn, hs, Ky);
            if (ix < 0.f || ix > 199.f || iy < 0.f || iy > 199.f) continue;
            int i0 = (int)ix;           // floor, ix >= 0
            int j0 = (int)iy;
            float fi = ix - (float)i0;
            float fj = iy - (float)j0;
            float wj = isj1 ? fj : (1.f - fj);
            unsigned base = ((unsigned)(i0*N2 + j0)) << 5;        // floats
            const unsigned iofs = (unsigned)(N2*2*N0);            // pad row: no select
            uint4 q0 = *((const uint4*)(st2 + base) + lane8);
            uint4 q1 = *((const uint4*)(st2 + base + iofs) + lane8);
            float w0 = wj * (1.f - fi);
            float w1 = wj * fi;
            unsigned long long w0p = f2_pack(w0, w0);
            unsigned long long w1p = f2_pack(w1, w1);
            f2_fma(acc01, w0p, f2_packu(q0.x, q0.y));
            f2_fma(acc01, w1p, f2_packu(q1.x, q1.y));
            f2_fma(acc23, w0p, f2_packu(q0.z, q0.w));
            f2_fma(acc23, w1p, f2_packu(q1.z, q1.w));
        }
    }

    // combine j0 (lanes 0-3) with j1 (lanes 4-7)
    acc01 = f2_add(acc01, __shfl_down_sync(0xffffffffu, acc01, 4));
    acc23 = f2_add(acc23, __shfl_down_sync(0xffffffffu, acc23, 4));

    if (live && !isj1) {
        int sidx = ray;
        float2 u01 = f2_unpack(acc01);
        float2 u23 = f2_unpack(acc23);
        float pr[4] = { u01.x*2.f, u01.y*2.f, u23.x*2.f, u23.y*2.f };
        float4 o;
        float* ov = (float*)&o;
        #pragma unroll
        for (int k = 0; k < 4; k++) {
            int gi = (zq*4 + k) * NSLOT + sidx;
            float mm = mult[gi];
            float e  = __fmaf_rn(mm, pr[k], contam[gi]);   // exp = mult*fwd + contam
            ov[k] = mm * data[gi] / e;                     // mult * (data/exp)
        }
        ((float4*)zr)[sidx*4 + zq] = o;
    }
}

// ---------------- backprojection (exact adjoint, gather form) ---------------
// one thread = (pixel, phi-chunk). All 16 z accumulated (packed f32x2).
// Interior pixels: pixel-centered weights, no bounds checks (tent support
// implies validity). Boundary pixels add the validity window test.
__global__ void k_backproject(const float* __restrict__ zr, float* __restrict__ bp)
{
    int tid = blockIdx.x * blockDim.x + threadIdx.x;
    if (tid >= NCH * NPIX) return;
    int pix = tid % NPIX;
    int ch  = tid / NPIX;
    int i = pix / N2, j = pix % N2;
    float X = -199.f + 2.f * (float)i;
    float Y = -199.f + 2.f * (float)j;

    unsigned long long accp[8];
    #pragma unroll
    for (int k = 0; k < 8; k++) accp[k] = 0ull;

    const float inv_dr = (float)(222.0 / 400.0);
    float cx = 99.5f - (float)i;     // 0.5*199 - i
    float cy = 99.5f - (float)j;
    // boundary validity windows: valid iff dx in [-i, 199-i], dy in [-j, 199-j]
    float vxl = -(float)i,  vxh = 199.f - (float)i;
    float vyl = -(float)j,  vyh = 199.f - (float)j;
    bool interior = (i >= 1 && i <= N1-2 && j >= 1 && j <= N2-2);

    int plo = ch * CHW;
    int phi_end = min(NPHI, plo + CHW);

    for (int phi = plo; phi < phi_end; phi++) {
        float c = d_COS[phi], s = d_SIN[phi];
        float lim = 2.f * (fabsf(c) + fabsf(s)) + 1e-2f;   // tight tent support
        float r0 = -X*s + Y*c;
        float t0 =  X*c + Y*s;
        int mlo = max(0,      (int)ceilf ((r0 + 200.f - lim) * inv_dr));
        int mhi = min(NRAD-1, (int)floorf((r0 + 200.f + lim) * inv_dr));
        int nlo = max(0,      (int)ceilf ((t0 + 350.f - lim) * 0.5f));
        int nhi = min(NT-1,   (int)floorf((t0 + 350.f + lim) * 0.5f));
        int ncnt = nhi - nlo;
        if (ncnt < 0 || mhi < mlo) continue;

        float hc = 0.5f * c, hs = 0.5f * s;
        float tn0 = -350.f + 2.f * (float)nlo;

        for (int m = mlo; m <= mhi; m++) {
            float rm = d_RV[m];
            float Kx = __fmaf_rn(rm, -hs, cx);   // dx(tn) = tn*hc + Kx = ix - i
            float Ky = __fmaf_rn(rm,  hc, cy);   // dy(tn) = tn*hs + Ky = iy - j
            float W = 0.f;
            if (interior) {
                float tn = tn0;
                for (int n = 0; n <= ncnt; n++, tn += 2.f) {
                    float dx = __fmaf_rn(tn, hc, Kx);
                    float dy = __fmaf_rn(tn, hs, Ky);
                    float wx = fmaxf(1.f - fabsf(dx), 0.f);
                    float wy = fmaxf(1.f - fabsf(dy), 0.f);
                    W = __fmaf_rn(wx, wy, W);
                }
            } else {
                float tn = tn0;
                for (int n = 0; n <= ncnt; n++, tn += 2.f) {
                    float dx = __fmaf_rn(tn, hc, Kx);
                    float dy = __fmaf_rn(tn, hs, Ky);
                    if (dx < vxl || dx > vxh || dy < vyl || dy > vyh) continue;
                    float wx = fmaxf(1.f - fabsf(dx), 0.f);
                    float wy = fmaxf(1.f - fabsf(dy), 0.f);
                    W = __fmaf_rn(wx, wy, W);
                }
            }
            if (W != 0.f) {
                const uint4* zp = (const uint4*)(zr + (phi*NRAD + m)*N0);
                uint4 a = zp[0], b = zp[1], cc2 = zp[2], dd = zp[3];
                unsigned long long Wp = f2_pack(W, W);
                f2_fma(accp[0], Wp, f2_packu(a.x,  a.y));
                f2_fma(accp[1], Wp, f2_packu(a.z,  a.w));
                f2_fma(accp[2], Wp, f2_packu(b.x,  b.y));
                f2_fma(accp[3], Wp, f2_packu(b.z,  b.w));
                f2_fma(accp[4], Wp, f2_packu(cc2.x, cc2.y));
                f2_fma(accp[5], Wp, f2_packu(cc2.z, cc2.w));
                f2_fma(accp[6], Wp, f2_packu(dd.x, dd.y));
                f2_fma(accp[7], Wp, f2_packu(dd.z, dd.w));
            }
        }
    }
    float* dst = bp + ch * NVOX;
    #pragma unroll
    for (int k = 0; k < 8; k++) {
        float2 u = f2_unpack(accp[k]);
        dst[(2*k  )*NPIX + pix] = u.x * 2.f;   // * STEP
        dst[(2*k+1)*NPIX + pix] = u.y * 2.f;
    }
}

// ---------------- combine partial backprojections (float4) ------------------
__global__ void k_combine(const float* __restrict__ bp, float* __restrict__ g)
{
    int t = blockIdx.x * blockDim.x + threadIdx.x;
    if (t >= NVOX/4) return;
    float4 s = make_float4(0.f, 0.f, 0.f, 0.f);
    #pragma unroll
    for (int c = 0; c < NCH; c++) {
        float4 v = ((const float4*)bp)[c*(NVOX/4) + t];
        s.x += v.x; s.y += v.y; s.z += v.z; s.w += v.w;
    }
    ((float4*)g)[t] = s;
}

// ---------------- adjoint gauss: fused j+z smooth ----------------------------
__global__ void k_smooth_jz(const float* __restrict__ in, float* __restrict__ out)
{
    __shared__ float tj[N0][N2 + 1];
    int i = blockIdx.x;
    for (int t = threadIdx.x; t < N0*N2; t += blockDim.x) {
        int j = t % N2;
        int z = t / N2;
        const float* base = in + z*NPIX + i*N2;
        float s = 0.f;
        if (j >= GR && j < N2-GR) {
            #pragma unroll
            for (int d = -GR; d <= GR; d++)
                s += d_GW[d+GR] * base[j+d];
        } else {
            #pragma unroll
            for (int d = -GR; d <= GR; d++)
                s += d_GW[d+GR] * base[refl(j+d, N2)];
        }
        tj[z][j] = s;
    }
    __syncthreads();
    for (int t = threadIdx.x; t < N0*N2; t += blockDim.x) {
        int j = t % N2;
        int z = t / N2;
        float s = 0.f;
        #pragma unroll
        for (int d = -GR; d <= GR; d++) {
            int m = z + d;
            if (m < 0)   m = -1 - m;
            if (m >= N0) m = 2*N0 - 1 - m;
            s += d_GW[d+GR] * tj[m][j];
        }
        out[z*NPIX + i*N2 + j] = s;
    }
}

// ---------------- adjoint i-smooth + MLEM update -----------------------------
__global__ void k_smooth_i_final(const float* __restrict__ gin,
                                 const float* __restrict__ x,
                                 const float* __restrict__ sens,
                                 float* __restrict__ out)
{
    int t = blockIdx.x * blockDim.x + threadIdx.x;
    if (t >= NVOX) return;
    int j = t % N2;
    int i = (t / N2) % N1;
    int z = t / NPIX;
    const float* base = gin + z*NPIX + j;
    float s = 0.f;
    if (i >= GR && i < N1-GR) {
        #pragma unroll
        for (int d = -GR; d <= GR; d++)
            s += d_GW[d+GR] * base[(i+d) * N2];
    } else {
        #pragma unroll
        for (int d = -GR; d <= GR; d++)
            s += d_GW[d+GR] * base[refl(i+d, N1) * N2];
    }
    out[t] = x[t] * s / sens[t];
}

// ---------------- launch ----------------------------------------------------
extern "C" void kernel_launch(void* const* d_in, const int* in_sizes, int n_in,
                              void* d_out, int out_size)
{
    const float* x      = (const float*)d_in[0];
    const float* data   = (const float*)d_in[1];
    const float* contam = (const float*)d_in[2];
    const float* mult   = (const float*)d_in[3];
    const float* sens   = (const float*)d_in[4];
    float* out = (float*)d_out;

    float *buf0, *buf1, *st2, *zr, *bp;
    cudaGetSymbolAddress((void**)&buf0, d_buf0);
    cudaGetSymbolAddress((void**)&buf1, d_buf1);
    cudaGetSymbolAddress((void**)&st2,  d_st2);
    cudaGetSymbolAddress((void**)&zr,   d_zr);
    cudaGetSymbolAddress((void**)&bp,   d_bp);

    k_init<<<1, 256>>>();

    // forward: fused gauss3 + paired transposed image (1 kernel)
    k_gauss3t2<<<N1, 512>>>(x, st2);

    // project + exp + ratio (fused, 8 lanes/ray)
    k_project<<<(NSLOT*8 + 255)/256, 256>>>(st2, data, contam, mult, zr);

    // adjoint: backproject (phi-chunked)  [4th launch -> ncu capture]
    k_backproject<<<(NCH*NPIX + 255)/256, 256>>>(zr, bp);
    k_combine<<<(NVOX/4 + 255)/256, 256>>>(bp, buf0);
    k_smooth_jz<<<N1, 512>>>(buf0, buf1);
    k_smooth_i_final<<<(NVOX + 255)/256, 256>>>(buf1, x, sens, out);
}